// round 2
// baseline (speedup 1.0000x reference)
#include <cuda_runtime.h>
#include <math.h>

// Cox partial likelihood (Breslow ties, mean reduction) via time-bucket histogram.
// time ∈ [0, 65536) -> no sort needed:
//   S[t]   = sum_{time_i==t} exp(x_i)
//   m[t]   = #events at time t
//   D[t]   = suffix sum of S  (risk-set denominator)
//   loss   = (sum_t m[t]*log(D[t]+eps) - sum_events x) / (n_events + eps)

#define NBUCKETS 65536
#define KCOPY 4

__device__ float  g_S[KCOPY * NBUCKETS];   // banked exp-sum histograms
__device__ int    g_m[KCOPY * NBUCKETS];   // banked event-count histograms
__device__ double g_acc[2];                // [0]=sum_events x, [1]=n_events

// ---------------------------------------------------------------------------
__global__ void zero_kernel() {
    int i = blockIdx.x * blockDim.x + threadIdx.x;
    int stride = gridDim.x * blockDim.x;
    for (int j = i; j < KCOPY * NBUCKETS; j += stride) {
        g_S[j] = 0.0f;
        g_m[j] = 0;
    }
    if (i < 2) g_acc[i] = 0.0;
}

// ---------------------------------------------------------------------------
__global__ void pass1_kernel(const float* __restrict__ x,
                             const int*   __restrict__ st,
                             const int*   __restrict__ tm,
                             int n) {
    int i  = blockIdx.x * blockDim.x + threadIdx.x;
    int i4 = i * 4;

    // bank selection by block to cut per-address atomic collisions
    float* S = g_S + (blockIdx.x & (KCOPY - 1)) * NBUCKETS;
    int*   M = g_m + (blockIdx.x & (KCOPY - 1)) * NBUCKETS;

    float ev_x = 0.0f;
    int   ev_c = 0;

    if (i4 + 3 < n) {
        float4 xv = *reinterpret_cast<const float4*>(x  + i4);
        int4   sv = *reinterpret_cast<const int4*>  (st + i4);
        int4   tv = *reinterpret_cast<const int4*>  (tm + i4);

        atomicAdd(&S[tv.x], __expf(xv.x));
        atomicAdd(&S[tv.y], __expf(xv.y));
        atomicAdd(&S[tv.z], __expf(xv.z));
        atomicAdd(&S[tv.w], __expf(xv.w));

        if (sv.x) { atomicAdd(&M[tv.x], 1); ev_x += xv.x; ev_c++; }
        if (sv.y) { atomicAdd(&M[tv.y], 1); ev_x += xv.y; ev_c++; }
        if (sv.z) { atomicAdd(&M[tv.z], 1); ev_x += xv.z; ev_c++; }
        if (sv.w) { atomicAdd(&M[tv.w], 1); ev_x += xv.w; ev_c++; }
    } else {
        for (int j = i4; j < n; j++) {
            float xs = x[j];
            atomicAdd(&S[tm[j]], __expf(xs));
            if (st[j]) { atomicAdd(&M[tm[j]], 1); ev_x += xs; ev_c++; }
        }
    }

    // block-reduce the event sums -> 2 double atomics per block
    __shared__ float  shx[32];
    __shared__ int    shc[32];
    int lane = threadIdx.x & 31;
    int wid  = threadIdx.x >> 5;
    #pragma unroll
    for (int o = 16; o > 0; o >>= 1) {
        ev_x += __shfl_down_sync(0xffffffffu, ev_x, o);
        ev_c += __shfl_down_sync(0xffffffffu, ev_c, o);
    }
    if (lane == 0) { shx[wid] = ev_x; shc[wid] = ev_c; }
    __syncthreads();
    int nw = blockDim.x >> 5;
    if (wid == 0) {
        ev_x = (lane < nw) ? shx[lane] : 0.0f;
        ev_c = (lane < nw) ? shc[lane] : 0;
        #pragma unroll
        for (int o = 16; o > 0; o >>= 1) {
            ev_x += __shfl_down_sync(0xffffffffu, ev_x, o);
            ev_c += __shfl_down_sync(0xffffffffu, ev_c, o);
        }
        if (lane == 0) {
            atomicAdd(&g_acc[0], (double)ev_x);
            atomicAdd(&g_acc[1], (double)ev_c);
        }
    }
}

// ---------------------------------------------------------------------------
// Single block: merge banks, suffix-scan 64K buckets, accumulate m[t]*log(D[t]+eps),
// combine with event sums, write the scalar loss.
__global__ void finalize_kernel(float* __restrict__ out) {
    const int T   = 1024;
    const int PER = NBUCKETS / T;      // 64 buckets per thread
    __shared__ double ssum[T];
    __shared__ double rsum[32];

    int tid  = threadIdx.x;
    int base = tid * PER;

    // chunk totals
    double chunk = 0.0;
    for (int j = 0; j < PER; j++) {
        int t = base + j;
        float s = 0.0f;
        #pragma unroll
        for (int k = 0; k < KCOPY; k++) s += g_S[k * NBUCKETS + t];
        chunk += (double)s;
    }
    ssum[tid] = chunk;
    __syncthreads();

    // suffix inclusive scan over chunk totals (Hillis-Steele)
    for (int off = 1; off < T; off <<= 1) {
        double v = (tid + off < T) ? ssum[tid + off] : 0.0;
        __syncthreads();
        ssum[tid] += v;
        __syncthreads();
    }

    // within-chunk descending accumulation; ssum[tid] = sum over chunks >= tid
    double running = ssum[tid] - chunk;   // exclusive suffix (chunks > tid)
    double nll = 0.0;
    for (int j = PER - 1; j >= 0; j--) {
        int t = base + j;
        float s = 0.0f;
        int   m = 0;
        #pragma unroll
        for (int k = 0; k < KCOPY; k++) {
            s += g_S[k * NBUCKETS + t];
            m += g_m[k * NBUCKETS + t];
        }
        running += (double)s;
        if (m) nll += (double)m * log(running + 1e-12);
    }

    // block reduce nll (1024 threads)
    int lane = tid & 31;
    int wid  = tid >> 5;
    #pragma unroll
    for (int o = 16; o > 0; o >>= 1)
        nll += __shfl_down_sync(0xffffffffu, nll, o);
    if (lane == 0) rsum[wid] = nll;
    __syncthreads();
    if (wid == 0) {
        nll = (lane < (T >> 5)) ? rsum[lane] : 0.0;
        #pragma unroll
        for (int o = 16; o > 0; o >>= 1)
            nll += __shfl_down_sync(0xffffffffu, nll, o);
        if (lane == 0) {
            double loss = (nll - g_acc[0]) / (g_acc[1] + 1e-12);
            out[0] = (float)loss;
        }
    }
}

// ---------------------------------------------------------------------------
extern "C" void kernel_launch(void* const* d_in, const int* in_sizes, int n_in,
                              void* d_out, int out_size) {
    const float* logits = (const float*)d_in[0];
    const int*   status = (const int*)d_in[1];
    const int*   timev  = (const int*)d_in[2];
    float*       out    = (float*)d_out;
    int n = in_sizes[0];

    zero_kernel<<<1024, 256>>>();

    int nThreads = (n + 3) / 4;
    int blocks   = (nThreads + 255) / 256;
    pass1_kernel<<<blocks, 256>>>(logits, status, timev, n);

    finalize_kernel<<<1, 1024>>>(out);
}

// round 3
// speedup vs baseline: 1.0918x; 1.0918x over previous
#include <cuda_runtime.h>
#include <math.h>

// Cox partial likelihood (Breslow ties, mean reduction) via time-bucket histogram.
// time ∈ [0, 65536):
//   S[t] = sum_{time_i==t} exp(x_i),  m[t] = #events at t
//   D[t] = suffix sum of S           (risk-set denominator)
//   loss = (sum_t m[t]*log(D[t]+eps) - sum_events x) / (n_events + eps)
//
// Round 2: per-CTA SHARED-MEMORY private histograms (2 passes over bucket
// ranges of 32K), plain-store flush to per-CTA global partials, then a
// parallel reduce + single-block suffix scan. Replaces 12.6M global REDs
// (L2 atomic-ALU bound) with smem atomics + 57MB of streaming stores.

#define NB     65536
#define G      148          // persistent CTAs (one per SM)
#define CHUNK  32768        // buckets per pass
#define NPASS  2
#define TPB    1024

__device__ float    g_partS[(size_t)G * NB];        // per-CTA exp-sum partials (38MB)
__device__ unsigned g_partM[(size_t)G * (NB / 2)];  // per-CTA packed u16x2 event counts (19MB)
__device__ float    g_Sfin[NB];
__device__ int      g_Mfin[NB];
__device__ double   g_acc[2];                       // [0]=sum_events x, [1]=n_events

// ---------------------------------------------------------------------------
__global__ void zero_kernel() {
    if (threadIdx.x < 2) g_acc[threadIdx.x] = 0.0;
}

// ---------------------------------------------------------------------------
extern __shared__ unsigned char smem_raw[];

__device__ __forceinline__ void process_elem(int t, float xv, int sv, int pass,
                                             float* sS, unsigned* sM,
                                             float& ev_x, int& ev_c) {
    if ((unsigned)t >> 15 == (unsigned)pass) {        // bucket in this pass's range
        int l = t & (CHUNK - 1);
        atomicAdd(&sS[l], __expf(xv));
        if (sv) atomicAdd(&sM[l >> 1], (l & 1) ? 65536u : 1u);
    }
    if (pass == 0 && sv) { ev_x += xv; ev_c++; }      // range-independent, count once
}

__global__ void __launch_bounds__(TPB, 1)
hist_kernel(const float* __restrict__ x,
            const int*   __restrict__ st,
            const int*   __restrict__ tm,
            int n, int lenPer) {
    float*    sS = (float*)smem_raw;                            // CHUNK floats
    unsigned* sM = (unsigned*)(smem_raw + CHUNK * sizeof(float)); // CHUNK/2 u32

    int c   = blockIdx.x;
    int tid = threadIdx.x;
    int s0  = c * lenPer;               // lenPer is a multiple of 4
    int s1  = min(s0 + lenPer, n);
    if (s0 > n) s0 = n;

    float ev_x = 0.0f;
    int   ev_c = 0;

    for (int pass = 0; pass < NPASS; pass++) {
        for (int i = tid; i < CHUNK; i += TPB)     sS[i] = 0.0f;
        for (int i = tid; i < CHUNK / 2; i += TPB) sM[i] = 0u;
        __syncthreads();

        // vectorized main loop over this CTA's slice
        int nfull4 = (s1 - s0) >> 2;                 // full float4 groups
        for (int g = tid; g < nfull4; g += TPB) {
            int idx = s0 + g * 4;
            float4 xv = *(const float4*)(x  + idx);
            int4   tv = *(const int4*)  (tm + idx);
            int4   sv = *(const int4*)  (st + idx);
            process_elem(tv.x, xv.x, sv.x, pass, sS, sM, ev_x, ev_c);
            process_elem(tv.y, xv.y, sv.y, pass, sS, sM, ev_x, ev_c);
            process_elem(tv.z, xv.z, sv.z, pass, sS, sM, ev_x, ev_c);
            process_elem(tv.w, xv.w, sv.w, pass, sS, sM, ev_x, ev_c);
        }
        // scalar tail (< 4 elements)
        int tail0 = s0 + nfull4 * 4;
        if (tid < s1 - tail0) {
            int idx = tail0 + tid;
            process_elem(tm[idx], x[idx], st[idx], pass, sS, sM, ev_x, ev_c);
        }
        __syncthreads();

        // flush private chunk with plain stores (no atomics)
        int base = pass * CHUNK;
        float*    dstS = g_partS + (size_t)c * NB + base;
        unsigned* dstM = g_partM + (size_t)c * (NB / 2) + base / 2;
        for (int i = tid; i < CHUNK; i += TPB)     dstS[i] = sS[i];
        for (int i = tid; i < CHUNK / 2; i += TPB) dstM[i] = sM[i];
        __syncthreads();
    }

    // block-reduce event sums -> 2 double REDs per CTA
    __shared__ float shx[32];
    __shared__ int   shc[32];
    int lane = tid & 31, wid = tid >> 5;
    #pragma unroll
    for (int o = 16; o > 0; o >>= 1) {
        ev_x += __shfl_down_sync(0xffffffffu, ev_x, o);
        ev_c += __shfl_down_sync(0xffffffffu, ev_c, o);
    }
    if (lane == 0) { shx[wid] = ev_x; shc[wid] = ev_c; }
    __syncthreads();
    if (wid == 0) {
        ev_x = (lane < TPB / 32) ? shx[lane] : 0.0f;
        ev_c = (lane < TPB / 32) ? shc[lane] : 0;
        #pragma unroll
        for (int o = 16; o > 0; o >>= 1) {
            ev_x += __shfl_down_sync(0xffffffffu, ev_x, o);
            ev_c += __shfl_down_sync(0xffffffffu, ev_c, o);
        }
        if (lane == 0) {
            atomicAdd(&g_acc[0], (double)ev_x);
            atomicAdd(&g_acc[1], (double)ev_c);
        }
    }
}

// ---------------------------------------------------------------------------
// Reduce G partial copies into final S[t], m[t]. One thread per bucket,
// coalesced across threads (stride-NB accesses per copy).
__global__ void reduce_kernel() {
    int t = blockIdx.x * blockDim.x + threadIdx.x;
    if (t >= NB) return;
    float s = 0.0f;
    int   m = 0;
    int   w = t >> 1;
    int   hi = t & 1;
    for (int c = 0; c < G; c++) {
        s += g_partS[(size_t)c * NB + t];
        unsigned pm = g_partM[(size_t)c * (NB / 2) + w];
        m += hi ? (int)(pm >> 16) : (int)(pm & 0xFFFFu);
    }
    g_Sfin[t] = s;
    g_Mfin[t] = m;
}

// ---------------------------------------------------------------------------
// Single block: suffix-scan 64K buckets (double), accumulate m[t]*log(D[t]+eps),
// combine with event sums, write the scalar loss.
__global__ void finalize_kernel(float* __restrict__ out) {
    const int T   = 1024;
    const int PER = NB / T;            // 64 buckets per thread
    __shared__ double ssum[T];
    __shared__ double rsum[32];

    int tid  = threadIdx.x;
    int base = tid * PER;

    double chunk = 0.0;
    for (int j = 0; j < PER; j++) chunk += (double)g_Sfin[base + j];
    ssum[tid] = chunk;
    __syncthreads();

    // suffix inclusive scan over per-thread chunk totals
    for (int off = 1; off < T; off <<= 1) {
        double v = (tid + off < T) ? ssum[tid + off] : 0.0;
        __syncthreads();
        ssum[tid] += v;
        __syncthreads();
    }

    double running = ssum[tid] - chunk;   // exclusive suffix (chunks > tid)
    double nll = 0.0;
    for (int j = PER - 1; j >= 0; j--) {
        int t = base + j;
        running += (double)g_Sfin[t];
        int m = g_Mfin[t];
        if (m) nll += (double)m * log(running + 1e-12);
    }

    int lane = tid & 31, wid = tid >> 5;
    #pragma unroll
    for (int o = 16; o > 0; o >>= 1)
        nll += __shfl_down_sync(0xffffffffu, nll, o);
    if (lane == 0) rsum[wid] = nll;
    __syncthreads();
    if (wid == 0) {
        nll = (lane < (T >> 5)) ? rsum[lane] : 0.0;
        #pragma unroll
        for (int o = 16; o > 0; o >>= 1)
            nll += __shfl_down_sync(0xffffffffu, nll, o);
        if (lane == 0) {
            double loss = (nll - g_acc[0]) / (g_acc[1] + 1e-12);
            out[0] = (float)loss;
        }
    }
}

// ---------------------------------------------------------------------------
extern "C" void kernel_launch(void* const* d_in, const int* in_sizes, int n_in,
                              void* d_out, int out_size) {
    const float* logits = (const float*)d_in[0];
    const int*   status = (const int*)d_in[1];
    const int*   timev  = (const int*)d_in[2];
    float*       out    = (float*)d_out;
    int n = in_sizes[0];

    // 192KB dynamic smem for the histogram kernel (idempotent, not an alloc)
    const int SMEM_BYTES = CHUNK * sizeof(float) + (CHUNK / 2) * sizeof(unsigned);
    cudaFuncSetAttribute(hist_kernel,
                         cudaFuncAttributeMaxDynamicSharedMemorySize, SMEM_BYTES);

    int lenPer = ((n + G - 1) / G + 3) & ~3;   // slice per CTA, multiple of 4

    zero_kernel<<<1, 32>>>();
    hist_kernel<<<G, TPB, SMEM_BYTES>>>(logits, status, timev, n, lenPer);
    reduce_kernel<<<NB / 256, 256>>>();
    finalize_kernel<<<1, 1024>>>(out);
}

// round 4
// speedup vs baseline: 9.2349x; 8.4586x over previous
#include <cuda_runtime.h>
#include <math.h>

// Cox partial likelihood (Breslow ties, mean reduction) via time-bucket histogram.
// time ∈ [0, 65536):
//   S[t] = sum_{time_i==t} exp(x_i),  m[t] = #events at t
//   D[t] = suffix sum of S           (risk-set denominator)
//   loss = (sum_t m[t]*log(D[t]+eps) - sum_events x) / (n_events + eps)
//
// Round 3: the epilogue (suffix scan + 64K double logs) is parallelized
// across the whole chip instead of one block (was 694us on a single SM).

#define NB     65536
#define G      148          // persistent CTAs (one per SM)
#define CHUNK  32768        // buckets per hist pass
#define NPASS  2
#define TPB    1024
#define NCHUNK 256          // epilogue chunks (256 buckets each)

__device__ float    g_partS[(size_t)G * NB];        // per-CTA exp-sum partials
__device__ unsigned g_partM[(size_t)G * (NB / 2)];  // per-CTA packed u16x2 event counts
__device__ float    g_Sfin[NB];
__device__ int      g_Mfin[NB];
__device__ double   g_chunkS[NCHUNK];               // per-chunk bucket-sum
__device__ double   g_chunkOff[NCHUNK];             // exclusive suffix offset per chunk
__device__ double   g_acc[3];                       // [0]=sum_events x, [1]=n_events, [2]=nll

// ---------------------------------------------------------------------------
__global__ void zero_kernel() {
    if (threadIdx.x < 3) g_acc[threadIdx.x] = 0.0;
}

// ---------------------------------------------------------------------------
extern __shared__ unsigned char smem_raw[];

__device__ __forceinline__ void process_elem(int t, float xv, int sv, int pass,
                                             float* sS, unsigned* sM,
                                             float& ev_x, int& ev_c) {
    if ((unsigned)t >> 15 == (unsigned)pass) {        // bucket in this pass's range
        int l = t & (CHUNK - 1);
        atomicAdd(&sS[l], __expf(xv));
        if (sv) atomicAdd(&sM[l >> 1], (l & 1) ? 65536u : 1u);
    }
    if (pass == 0 && sv) { ev_x += xv; ev_c++; }      // range-independent, count once
}

__global__ void __launch_bounds__(TPB, 1)
hist_kernel(const float* __restrict__ x,
            const int*   __restrict__ st,
            const int*   __restrict__ tm,
            int n, int lenPer) {
    float*    sS = (float*)smem_raw;                              // CHUNK floats
    unsigned* sM = (unsigned*)(smem_raw + CHUNK * sizeof(float)); // CHUNK/2 u32

    int c   = blockIdx.x;
    int tid = threadIdx.x;
    int s0  = c * lenPer;               // lenPer is a multiple of 4
    int s1  = min(s0 + lenPer, n);
    if (s0 > n) s0 = n;

    float ev_x = 0.0f;
    int   ev_c = 0;

    for (int pass = 0; pass < NPASS; pass++) {
        for (int i = tid; i < CHUNK; i += TPB)     sS[i] = 0.0f;
        for (int i = tid; i < CHUNK / 2; i += TPB) sM[i] = 0u;
        __syncthreads();

        int nfull4 = (s1 - s0) >> 2;                 // full float4 groups
        for (int g = tid; g < nfull4; g += TPB) {
            int idx = s0 + g * 4;
            float4 xv = *(const float4*)(x  + idx);
            int4   tv = *(const int4*)  (tm + idx);
            int4   sv = *(const int4*)  (st + idx);
            process_elem(tv.x, xv.x, sv.x, pass, sS, sM, ev_x, ev_c);
            process_elem(tv.y, xv.y, sv.y, pass, sS, sM, ev_x, ev_c);
            process_elem(tv.z, xv.z, sv.z, pass, sS, sM, ev_x, ev_c);
            process_elem(tv.w, xv.w, sv.w, pass, sS, sM, ev_x, ev_c);
        }
        int tail0 = s0 + nfull4 * 4;
        if (tid < s1 - tail0) {
            int idx = tail0 + tid;
            process_elem(tm[idx], x[idx], st[idx], pass, sS, sM, ev_x, ev_c);
        }
        __syncthreads();

        // flush private chunk with plain stores (no atomics)
        int base = pass * CHUNK;
        float*    dstS = g_partS + (size_t)c * NB + base;
        unsigned* dstM = g_partM + (size_t)c * (NB / 2) + base / 2;
        for (int i = tid; i < CHUNK; i += TPB)     dstS[i] = sS[i];
        for (int i = tid; i < CHUNK / 2; i += TPB) dstM[i] = sM[i];
        __syncthreads();
    }

    // block-reduce event sums -> 2 double REDs per CTA
    __shared__ float shx[32];
    __shared__ int   shc[32];
    int lane = tid & 31, wid = tid >> 5;
    #pragma unroll
    for (int o = 16; o > 0; o >>= 1) {
        ev_x += __shfl_down_sync(0xffffffffu, ev_x, o);
        ev_c += __shfl_down_sync(0xffffffffu, ev_c, o);
    }
    if (lane == 0) { shx[wid] = ev_x; shc[wid] = ev_c; }
    __syncthreads();
    if (wid == 0) {
        ev_x = (lane < TPB / 32) ? shx[lane] : 0.0f;
        ev_c = (lane < TPB / 32) ? shc[lane] : 0;
        #pragma unroll
        for (int o = 16; o > 0; o >>= 1) {
            ev_x += __shfl_down_sync(0xffffffffu, ev_x, o);
            ev_c += __shfl_down_sync(0xffffffffu, ev_c, o);
        }
        if (lane == 0) {
            atomicAdd(&g_acc[0], (double)ev_x);
            atomicAdd(&g_acc[1], (double)ev_c);
        }
    }
}

// ---------------------------------------------------------------------------
// 256 blocks x 256 threads: bucket t = blockIdx*256 + tid.
// Merge G partial copies -> S[t], m[t]; also block-reduce chunk sum.
__global__ void reduce_kernel() {
    __shared__ double rs[32];
    int tid = threadIdx.x;
    int t   = blockIdx.x * 256 + tid;
    float s = 0.0f;
    int   m = 0;
    int   w = t >> 1;
    int   hi = t & 1;
    for (int c = 0; c < G; c++) {
        s += g_partS[(size_t)c * NB + t];
        unsigned pm = g_partM[(size_t)c * (NB / 2) + w];
        m += hi ? (int)(pm >> 16) : (int)(pm & 0xFFFFu);
    }
    g_Sfin[t] = s;
    g_Mfin[t] = m;

    // chunk sum (double)
    double d = (double)s;
    int lane = tid & 31, wid = tid >> 5;
    #pragma unroll
    for (int o = 16; o > 0; o >>= 1)
        d += __shfl_down_sync(0xffffffffu, d, o);
    if (lane == 0) rs[wid] = d;
    __syncthreads();
    if (wid == 0) {
        d = (lane < 8) ? rs[lane] : 0.0;
        #pragma unroll
        for (int o = 4; o > 0; o >>= 1)
            d += __shfl_down_sync(0xffffffffu, d, o);
        if (lane == 0) g_chunkS[blockIdx.x] = d;
    }
}

// ---------------------------------------------------------------------------
// Single block, 256 threads: exclusive suffix scan over chunk sums.
__global__ void scan_kernel() {
    __shared__ double s[NCHUNK];
    int tid = threadIdx.x;
    double own = g_chunkS[tid];
    s[tid] = own;
    __syncthreads();
    for (int off = 1; off < NCHUNK; off <<= 1) {
        double v = (tid + off < NCHUNK) ? s[tid + off] : 0.0;
        __syncthreads();
        s[tid] += v;
        __syncthreads();
    }
    g_chunkOff[tid] = s[tid] - own;   // exclusive: sum over chunks > tid
}

// ---------------------------------------------------------------------------
// 256 blocks x 256 threads: intra-chunk suffix scan + per-bucket log,
// block-reduce nll, one double RED per block.
__global__ void nll_kernel() {
    __shared__ double suf[256];
    __shared__ double rs[32];
    int tid = threadIdx.x;
    int t   = blockIdx.x * 256 + tid;

    double sv = (double)g_Sfin[t];
    int    m  = g_Mfin[t];

    suf[tid] = sv;
    __syncthreads();
    for (int off = 1; off < 256; off <<= 1) {
        double v = (tid + off < 256) ? suf[tid + off] : 0.0;
        __syncthreads();
        suf[tid] += v;
        __syncthreads();
    }
    double D = suf[tid] + g_chunkOff[blockIdx.x];   // inclusive suffix incl. later chunks
    double nll = m ? (double)m * log(D + 1e-12) : 0.0;

    int lane = tid & 31, wid = tid >> 5;
    #pragma unroll
    for (int o = 16; o > 0; o >>= 1)
        nll += __shfl_down_sync(0xffffffffu, nll, o);
    if (lane == 0) rs[wid] = nll;
    __syncthreads();
    if (wid == 0) {
        nll = (lane < 8) ? rs[lane] : 0.0;
        #pragma unroll
        for (int o = 4; o > 0; o >>= 1)
            nll += __shfl_down_sync(0xffffffffu, nll, o);
        if (lane == 0) atomicAdd(&g_acc[2], nll);
    }
}

// ---------------------------------------------------------------------------
__global__ void write_kernel(float* __restrict__ out) {
    out[0] = (float)((g_acc[2] - g_acc[0]) / (g_acc[1] + 1e-12));
}

// ---------------------------------------------------------------------------
extern "C" void kernel_launch(void* const* d_in, const int* in_sizes, int n_in,
                              void* d_out, int out_size) {
    const float* logits = (const float*)d_in[0];
    const int*   status = (const int*)d_in[1];
    const int*   timev  = (const int*)d_in[2];
    float*       out    = (float*)d_out;
    int n = in_sizes[0];

    const int SMEM_BYTES = CHUNK * sizeof(float) + (CHUNK / 2) * sizeof(unsigned);
    cudaFuncSetAttribute(hist_kernel,
                         cudaFuncAttributeMaxDynamicSharedMemorySize, SMEM_BYTES);

    int lenPer = ((n + G - 1) / G + 3) & ~3;   // slice per CTA, multiple of 4

    zero_kernel<<<1, 32>>>();
    hist_kernel<<<G, TPB, SMEM_BYTES>>>(logits, status, timev, n, lenPer);
    reduce_kernel<<<NCHUNK, 256>>>();
    scan_kernel<<<1, NCHUNK>>>();
    nll_kernel<<<NCHUNK, 256>>>();
    write_kernel<<<1, 1>>>(out);
}